// round 6
// baseline (speedup 1.0000x reference)
#include <cuda_runtime.h>
#include <cuda_fp16.h>

#define N_NODES  100000
#define N_EDGES  3200000
#define N_GRAPHS 128

// ---------------- scratch (static device globals; no runtime alloc) ----------
__device__ int   g_cnt[N_NODES];
__device__ int   g_rowptr[N_NODES];            // after k_fill: END of each row
__device__ int   g_bsums[128];
__device__ float g_dinv[N_NODES];
__device__ __align__(16) int2 g_csr[N_EDGES];      // {src, float_bits(dinv[src])}
__device__ __align__(16) __half g_h16a[N_NODES * 64];  // activations fp16 (layers 1,3)
__device__ __align__(16) __half g_h16b[N_NODES * 64];  // activations fp16 (layer 2)
__device__ __align__(16) float g_pool[N_GRAPHS * 64];

// half(nonneg)->float bit tricks; result is 2^-112 * true_value; compensated once
// per node (exact incl. subnormals; activations are post-ReLU so sign bit is 0).
__device__ __forceinline__ float h2f_lo(unsigned v) { return __int_as_float((v & 0xffffu) << 13); }
__device__ __forceinline__ float h2f_hi(unsigned v) { return __int_as_float((v >> 3) & 0x1FFFE000u); }

// ---------------- degree histogram ----------------
__global__ void k_zero_cnt() {
    int i = blockIdx.x * blockDim.x + threadIdx.x;
    if (i < N_NODES) g_cnt[i] = 0;
}

__global__ void k_hist(const int4* __restrict__ dst4) {
    int i = blockIdx.x * blockDim.x + threadIdx.x;   // N_EDGES/4 threads
    int4 d = __ldg(&dst4[i]);
    atomicAdd(&g_cnt[d.x], 1);
    atomicAdd(&g_cnt[d.y], 1);
    atomicAdd(&g_cnt[d.z], 1);
    atomicAdd(&g_cnt[d.w], 1);
}

// ---------------- exclusive scan over 100k counts (2 kernels) ----------------
__global__ void k_scan_blocks() {
    __shared__ int s[1024];
    int tid = threadIdx.x;
    int i = blockIdx.x * 1024 + tid;
    int v = (i < N_NODES) ? g_cnt[i] : 0;
    s[tid] = v;
    __syncthreads();
    for (int off = 1; off < 1024; off <<= 1) {
        int t = (tid >= off) ? s[tid - off] : 0;
        __syncthreads();
        s[tid] += t;
        __syncthreads();
    }
    if (i < N_NODES) g_rowptr[i] = s[tid] - v;   // exclusive within block
    if (tid == 1023) g_bsums[blockIdx.x] = s[1023];
}

__global__ void k_scan_add() {
    __shared__ int s_pre;
    int tid = threadIdx.x;
    if (tid < 32) {
        int acc = 0;
        for (int b = tid; b < blockIdx.x; b += 32) acc += g_bsums[b];
        for (int off = 16; off > 0; off >>= 1) acc += __shfl_xor_sync(0xffffffffu, acc, off);
        if (tid == 0) s_pre = acc;
    }
    __syncthreads();
    int i = blockIdx.x * 1024 + tid;
    if (i < N_NODES) {
        g_rowptr[i] += s_pre;
        g_dinv[i] = rsqrtf((float)(g_cnt[i] + 1));   // +1 self loop
    }
}

// ---------------- CSR fill: rowptr itself is the cursor (becomes row END) ----
__global__ void k_fill(const int4* __restrict__ src4, const int4* __restrict__ dst4) {
    int i = blockIdx.x * blockDim.x + threadIdx.x;   // N_EDGES/4 threads
    int4 s = __ldg(&src4[i]);
    int4 d = __ldg(&dst4[i]);
    {
        int pos = atomicAdd(&g_rowptr[d.x], 1);
        g_csr[pos] = make_int2(s.x, __float_as_int(g_dinv[s.x]));
    }
    {
        int pos = atomicAdd(&g_rowptr[d.y], 1);
        g_csr[pos] = make_int2(s.y, __float_as_int(g_dinv[s.y]));
    }
    {
        int pos = atomicAdd(&g_rowptr[d.z], 1);
        g_csr[pos] = make_int2(s.z, __float_as_int(g_dinv[s.z]));
    }
    {
        int pos = atomicAdd(&g_rowptr[d.w], 1);
        g_csr[pos] = make_int2(s.w, __float_as_int(g_dinv[s.w]));
    }
}

// ---------------- layer 1 fused: agg(x,16) then @W1[16,64]+b1, relu -> h16a --
__global__ void k_agg16_mm1(const float* __restrict__ x,
                            const float* __restrict__ W1, const float* __restrict__ b1) {
    __shared__ float2 sW[16 * 32];
    __shared__ float2 sB[32];
    int tid = threadIdx.x;
    for (int idx = tid; idx < 16 * 32; idx += 256) sW[idx] = __ldg((const float2*)W1 + idx);
    if (tid < 32) sB[tid] = __ldg((const float2*)b1 + tid);
    __syncthreads();

    int w = (blockIdx.x * 256 + tid) >> 5;
    if (w >= N_NODES) return;
    int lane = tid & 31;
    int sub = lane >> 4, c = lane & 15;
    int e1 = __ldg(&g_rowptr[w]);
    int e0 = e1 - __ldg(&g_cnt[w]);
    float dv = g_dinv[w];
    // self loop: x[w]*dv here, *dv again at the end -> dv^2
    float a = (sub == 0) ? __ldg(&x[(size_t)w * 16 + c]) * dv : 0.f;
    int k = e0 + sub;
    for (; k + 6 < e1; k += 8) {       // 4 edges per sub in flight
        int2 c0 = __ldg(&g_csr[k]);
        int2 c1 = __ldg(&g_csr[k + 2]);
        int2 c2 = __ldg(&g_csr[k + 4]);
        int2 c3 = __ldg(&g_csr[k + 6]);
        float v0 = __ldg(&x[(size_t)c0.x * 16 + c]);
        float v1 = __ldg(&x[(size_t)c1.x * 16 + c]);
        float v2 = __ldg(&x[(size_t)c2.x * 16 + c]);
        float v3 = __ldg(&x[(size_t)c3.x * 16 + c]);
        a = fmaf(v0, __int_as_float(c0.y), a);
        a = fmaf(v1, __int_as_float(c1.y), a);
        a = fmaf(v2, __int_as_float(c2.y), a);
        a = fmaf(v3, __int_as_float(c3.y), a);
    }
    for (; k < e1; k += 2) {
        int2 cw = __ldg(&g_csr[k]);
        a = fmaf(__ldg(&x[(size_t)cw.x * 16 + c]), __int_as_float(cw.y), a);
    }
    a *= dv;                                     // dinv[dst] factored out
    a += __shfl_xor_sync(0xffffffffu, a, 16);    // combine subs; lane has a[lane&15]

    // mm 16 -> 64: lane computes cols {2*lane, 2*lane+1}
    float2 acc = sB[lane];
#pragma unroll
    for (int kk = 0; kk < 16; kk++) {
        float ak = __shfl_sync(0xffffffffu, a, kk);
        float2 wv = sW[kk * 32 + lane];
        acc.x = fmaf(ak, wv.x, acc.x);
        acc.y = fmaf(ak, wv.y, acc.y);
    }
    __half2 hv = __floats2half2_rn(fmaxf(acc.x, 0.f), fmaxf(acc.y, 0.f));
    ((__half2*)g_h16a)[(size_t)w * 32 + lane] = hv;
}

// ---------------- fused 64-wide aggregation + 64x64 matmul + relu ------------
// warp per node; gathers fp16 rows, combines, then applies W (from smem) and
// writes fp16 activations directly (no fp32 roundtrip through memory).
template <int SRC>
__global__ void k_agg64_mm(const float* __restrict__ Wm, const float* __restrict__ bv) {
    const __half* __restrict__ h = (SRC == 0) ? g_h16a : g_h16b;
    __half2* __restrict__ out = (__half2*)((SRC == 0) ? g_h16b : g_h16a);
    __shared__ float2 sW[64 * 32];   // sW[k*32+l] = {W[k][2l], W[k][2l+1]}
    __shared__ float2 sB[32];
    int tid = threadIdx.x;
    for (int idx = tid; idx < 64 * 32; idx += 256) sW[idx] = __ldg((const float2*)Wm + idx);
    if (tid < 32) sB[tid] = __ldg((const float2*)bv + tid);
    __syncthreads();

    int w = (blockIdx.x * 256 + tid) >> 5;
    if (w >= N_NODES) return;
    int lane = tid & 31;
    int sub = lane >> 4, t = lane & 15;
    int e1 = __ldg(&g_rowptr[w]);
    int e0 = e1 - __ldg(&g_cnt[w]);
    float dv = g_dinv[w];

    // self loop contribution (sub0 only; *dv here, *(dv*2^112) at the end -> dv^2)
    uint2 sv = __ldg((const uint2*)(h + (size_t)w * 64) + t);
    float ws = (sub == 0) ? dv : 0.f;
    float4 acc;
    acc.x = h2f_lo(sv.x) * ws;
    acc.y = h2f_hi(sv.x) * ws;
    acc.z = h2f_lo(sv.y) * ws;
    acc.w = h2f_hi(sv.y) * ws;

    int k = e0 + sub;
    for (; k + 6 < e1; k += 8) {       // 4 edges per sub: 4 csr + 4 feature loads in flight
        int2 c0 = __ldg(&g_csr[k]);
        int2 c1 = __ldg(&g_csr[k + 2]);
        int2 c2 = __ldg(&g_csr[k + 4]);
        int2 c3 = __ldg(&g_csr[k + 6]);
        uint2 f0 = __ldg((const uint2*)(h + (size_t)c0.x * 64) + t);
        uint2 f1 = __ldg((const uint2*)(h + (size_t)c1.x * 64) + t);
        uint2 f2 = __ldg((const uint2*)(h + (size_t)c2.x * 64) + t);
        uint2 f3 = __ldg((const uint2*)(h + (size_t)c3.x * 64) + t);
        float w0 = __int_as_float(c0.y), w1 = __int_as_float(c1.y);
        float w2 = __int_as_float(c2.y), w3 = __int_as_float(c3.y);
        acc.x = fmaf(h2f_lo(f0.x), w0, acc.x);
        acc.y = fmaf(h2f_hi(f0.x), w0, acc.y);
        acc.z = fmaf(h2f_lo(f0.y), w0, acc.z);
        acc.w = fmaf(h2f_hi(f0.y), w0, acc.w);
        acc.x = fmaf(h2f_lo(f1.x), w1, acc.x);
        acc.y = fmaf(h2f_hi(f1.x), w1, acc.y);
        acc.z = fmaf(h2f_lo(f1.y), w1, acc.z);
        acc.w = fmaf(h2f_hi(f1.y), w1, acc.w);
        acc.x = fmaf(h2f_lo(f2.x), w2, acc.x);
        acc.y = fmaf(h2f_hi(f2.x), w2, acc.y);
        acc.z = fmaf(h2f_lo(f2.y), w2, acc.z);
        acc.w = fmaf(h2f_hi(f2.y), w2, acc.w);
        acc.x = fmaf(h2f_lo(f3.x), w3, acc.x);
        acc.y = fmaf(h2f_hi(f3.x), w3, acc.y);
        acc.z = fmaf(h2f_lo(f3.y), w3, acc.z);
        acc.w = fmaf(h2f_hi(f3.y), w3, acc.w);
    }
    for (; k < e1; k += 2) {
        int2 cw = __ldg(&g_csr[k]);
        float wv = __int_as_float(cw.y);
        uint2 f = __ldg((const uint2*)(h + (size_t)cw.x * 64) + t);
        acc.x = fmaf(h2f_lo(f.x), wv, acc.x);
        acc.y = fmaf(h2f_hi(f.x), wv, acc.y);
        acc.z = fmaf(h2f_lo(f.y), wv, acc.z);
        acc.w = fmaf(h2f_hi(f.y), wv, acc.w);
    }
    // apply dinv[dst] + fp16-decode compensation, then combine halves.
    // After the xor-combine ALL lanes hold the full node vector (4 cols each).
    float fs = dv * 0x1p112f;
    acc.x *= fs; acc.y *= fs; acc.z *= fs; acc.w *= fs;
    acc.x += __shfl_xor_sync(0xffffffffu, acc.x, 16);
    acc.y += __shfl_xor_sync(0xffffffffu, acc.y, 16);
    acc.z += __shfl_xor_sync(0xffffffffu, acc.z, 16);
    acc.w += __shfl_xor_sync(0xffffffffu, acc.w, 16);

    // fused 64x64 matmul: lane computes output cols {2*lane, 2*lane+1}
    float2 o = sB[lane];
#pragma unroll
    for (int s = 0; s < 16; s++) {      // lane s holds agg cols 4s..4s+3
        float ax = __shfl_sync(0xffffffffu, acc.x, s);
        float ay = __shfl_sync(0xffffffffu, acc.y, s);
        float az = __shfl_sync(0xffffffffu, acc.z, s);
        float aw = __shfl_sync(0xffffffffu, acc.w, s);
        float2 w0 = sW[(4 * s + 0) * 32 + lane];
        float2 w1 = sW[(4 * s + 1) * 32 + lane];
        float2 w2 = sW[(4 * s + 2) * 32 + lane];
        float2 w3 = sW[(4 * s + 3) * 32 + lane];
        o.x = fmaf(ax, w0.x, o.x); o.y = fmaf(ax, w0.y, o.y);
        o.x = fmaf(ay, w1.x, o.x); o.y = fmaf(ay, w1.y, o.y);
        o.x = fmaf(az, w2.x, o.x); o.y = fmaf(az, w2.y, o.y);
        o.x = fmaf(aw, w3.x, o.x); o.y = fmaf(aw, w3.y, o.y);
    }
    __half2 hv = __floats2half2_rn(fmaxf(o.x, 0.f), fmaxf(o.y, 0.f));
    out[(size_t)w * 32 + lane] = hv;
}

// ---------------- mean pool per graph (batch sorted); reads g_h16a -----------
__global__ void k_pool(const int* __restrict__ batch) {
    int g = blockIdx.x;
    int lo = 0, hi = N_NODES;
    while (lo < hi) { int mid = (lo + hi) >> 1; if (__ldg(&batch[mid]) < g) lo = mid + 1; else hi = mid; }
    int start = lo;
    lo = start; hi = N_NODES;
    while (lo < hi) { int mid = (lo + hi) >> 1; if (__ldg(&batch[mid]) < g + 1) lo = mid + 1; else hi = mid; }
    int end = lo;

    __shared__ float2 sp[8][32];
    int cp = threadIdx.x & 31, rg = threadIdx.x >> 5;
    float2 acc = make_float2(0.f, 0.f);
    const __half2* h2 = (const __half2*)g_h16a;
    for (int r = start + rg; r < end; r += 8) {
        float2 f = __half22float2(h2[(size_t)r * 32 + cp]);
        acc.x += f.x; acc.y += f.y;
    }
    sp[rg][cp] = acc;
    __syncthreads();
    if (rg == 0) {
        float2 t = sp[0][cp];
#pragma unroll
        for (int i = 1; i < 8; i++) { t.x += sp[i][cp].x; t.y += sp[i][cp].y; }
        float cnt = (float)(end - start);
        if (cnt < 1.f) cnt = 1.f;
        ((float2*)g_pool)[g * 32 + cp] = make_float2(t.x / cnt, t.y / cnt);
    }
}

// ---------------- MLP head ----------------
__global__ void k_head(const float* __restrict__ Wf1, const float* __restrict__ bf1,
                       const float* __restrict__ Wf2, const float* __restrict__ bf2,
                       float* __restrict__ out) {
    int g = threadIdx.x;
    if (g >= N_GRAPHS) return;
    float p[64];
#pragma unroll
    for (int k = 0; k < 64; k++) p[k] = g_pool[g * 64 + k];
    float o = __ldg(&bf2[0]);
#pragma unroll 4
    for (int j = 0; j < 32; j++) {
        float hj = __ldg(&bf1[j]);
#pragma unroll
        for (int k = 0; k < 64; k++) hj = fmaf(p[k], __ldg(&Wf1[k * 32 + j]), hj);
        o = fmaf(fmaxf(hj, 0.f), __ldg(&Wf2[j]), o);
    }
    out[g] = o;
}

// ---------------- launch ----------------
extern "C" void kernel_launch(void* const* d_in, const int* in_sizes, int n_in,
                              void* d_out, int out_size) {
    const float* x   = (const float*)d_in[0];
    const int*   ei  = (const int*)d_in[1];
    const int4*  src4 = (const int4*)ei;
    const int4*  dst4 = (const int4*)(ei + N_EDGES);
    const int*   batch = (const int*)d_in[3];
    const float* W1 = (const float*)d_in[4];  const float* b1 = (const float*)d_in[5];
    const float* W2 = (const float*)d_in[6];  const float* b2 = (const float*)d_in[7];
    const float* W3 = (const float*)d_in[8];  const float* b3 = (const float*)d_in[9];
    const float* Wf1 = (const float*)d_in[10]; const float* bf1 = (const float*)d_in[11];
    const float* Wf2 = (const float*)d_in[12]; const float* bf2 = (const float*)d_in[13];
    float* out = (float*)d_out;

    const int nb_scan = (N_NODES + 1023) / 1024;       // 98
    const int eb4 = (N_EDGES / 4) / 256;               // 3125
    const int wb = (N_NODES * 32 + 255) / 256;         // one warp per node: 12500

    k_zero_cnt<<<(N_NODES + 255) / 256, 256>>>();
    k_hist<<<eb4, 256>>>(dst4);
    k_scan_blocks<<<nb_scan, 1024>>>();
    k_scan_add<<<nb_scan, 1024>>>();
    k_fill<<<eb4, 256>>>(src4, dst4);

    k_agg16_mm1<<<wb, 256>>>(x, W1, b1);     // layer 1 fused -> h16a
    k_agg64_mm<0><<<wb, 256>>>(W2, b2);      // gather h16a, mm W2 -> h16b
    k_agg64_mm<1><<<wb, 256>>>(W3, b3);      // gather h16b, mm W3 -> h16a

    k_pool<<<N_GRAPHS, 256>>>(batch);
    k_head<<<1, 128>>>(Wf1, bf1, Wf2, bf2, out);
}

// round 7
// speedup vs baseline: 1.2453x; 1.2453x over previous
#include <cuda_runtime.h>
#include <cuda_fp16.h>

#define N_NODES  100000
#define N_EDGES  3200000
#define N_GRAPHS 128

// ---------------- scratch (static device globals; no runtime alloc) ----------
__device__ int   g_cnt[N_NODES];
__device__ int   g_rowptr[N_NODES];            // after k_fill: END of each row
__device__ int   g_bsums[128];
__device__ float g_dinv[N_NODES];
__device__ int   g_csr[N_EDGES];               // src only (features pre-scaled by dinv)
__device__ __align__(16) float g_xs[N_NODES * 16];     // x * dinv[node]
__device__ __align__(16) float g_bufa[N_NODES * 64];   // agg output (fp32)
__device__ __align__(16) __half g_h16a[N_NODES * 64];  // activations fp16 (L1 scaled, L3 raw)
__device__ __align__(16) __half g_h16b[N_NODES * 64];  // activations fp16 (L2 scaled)
__device__ __align__(16) float g_pool[N_GRAPHS * 64];

// half(nonneg)->float bit tricks; result is 2^-112 * true_value; compensated once
// per node (exact incl. subnormals; activations are post-ReLU so sign bit is 0).
__device__ __forceinline__ float h2f_lo(unsigned v) { return __int_as_float((v & 0xffffu) << 13); }
__device__ __forceinline__ float h2f_hi(unsigned v) { return __int_as_float((v >> 3) & 0x1FFFE000u); }

// ---------------- degree histogram ----------------
__global__ void k_zero_cnt() {
    int i = blockIdx.x * blockDim.x + threadIdx.x;
    if (i < N_NODES) g_cnt[i] = 0;
}

__global__ void k_hist(const int4* __restrict__ dst4) {
    int i = blockIdx.x * blockDim.x + threadIdx.x;   // N_EDGES/4 threads
    int4 d = __ldg(&dst4[i]);
    atomicAdd(&g_cnt[d.x], 1);
    atomicAdd(&g_cnt[d.y], 1);
    atomicAdd(&g_cnt[d.z], 1);
    atomicAdd(&g_cnt[d.w], 1);
}

// ---------------- exclusive scan over 100k counts (2 kernels) ----------------
__global__ void k_scan_blocks() {
    __shared__ int s[1024];
    int tid = threadIdx.x;
    int i = blockIdx.x * 1024 + tid;
    int v = (i < N_NODES) ? g_cnt[i] : 0;
    s[tid] = v;
    __syncthreads();
    for (int off = 1; off < 1024; off <<= 1) {
        int t = (tid >= off) ? s[tid - off] : 0;
        __syncthreads();
        s[tid] += t;
        __syncthreads();
    }
    if (i < N_NODES) g_rowptr[i] = s[tid] - v;   // exclusive within block
    if (tid == 1023) g_bsums[blockIdx.x] = s[1023];
}

// scan finish + dinv + pre-scaled x (fused; no extra launch)
__global__ void k_scan_add(const float* __restrict__ x) {
    __shared__ int s_pre;
    int tid = threadIdx.x;
    if (tid < 32) {
        int acc = 0;
        for (int b = tid; b < blockIdx.x; b += 32) acc += g_bsums[b];
        for (int off = 16; off > 0; off >>= 1) acc += __shfl_xor_sync(0xffffffffu, acc, off);
        if (tid == 0) s_pre = acc;
    }
    __syncthreads();
    int i = blockIdx.x * 1024 + tid;
    if (i < N_NODES) {
        g_rowptr[i] += s_pre;
        float dv = rsqrtf((float)(g_cnt[i] + 1));   // +1 self loop
        g_dinv[i] = dv;
        const float4* xr = (const float4*)(x + (size_t)i * 16);
        float4* xo = (float4*)(g_xs + (size_t)i * 16);
#pragma unroll
        for (int c = 0; c < 4; c++) {
            float4 v = __ldg(&xr[c]);
            v.x *= dv; v.y *= dv; v.z *= dv; v.w *= dv;
            xo[c] = v;
        }
    }
}

// ---------------- CSR fill: rowptr itself is the cursor (becomes row END) ----
__global__ void k_fill(const int4* __restrict__ src4, const int4* __restrict__ dst4) {
    int i = blockIdx.x * blockDim.x + threadIdx.x;   // N_EDGES/4 threads
    int4 s = __ldg(&src4[i]);
    int4 d = __ldg(&dst4[i]);
    g_csr[atomicAdd(&g_rowptr[d.x], 1)] = s.x;
    g_csr[atomicAdd(&g_rowptr[d.y], 1)] = s.y;
    g_csr[atomicAdd(&g_rowptr[d.z], 1)] = s.z;
    g_csr[atomicAdd(&g_rowptr[d.w], 1)] = s.w;
}

// ---------------- layer 1 fused: agg(xs,16) then @W1[16,64]+b1, relu --------
// writes h16a PRE-SCALED by dinv[w] for layer-2 consumption.
__global__ void k_agg16_mm1(const float* __restrict__ W1, const float* __restrict__ b1) {
    __shared__ float2 sW[16 * 32];
    __shared__ float2 sB[32];
    int tid = threadIdx.x;
    for (int idx = tid; idx < 16 * 32; idx += 256) sW[idx] = __ldg((const float2*)W1 + idx);
    if (tid < 32) sB[tid] = __ldg((const float2*)b1 + tid);
    __syncthreads();

    int w = (blockIdx.x * 256 + tid) >> 5;
    if (w >= N_NODES) return;
    int lane = tid & 31;
    int sub = lane >> 4, c = lane & 15;
    int e1 = __ldg(&g_rowptr[w]);
    int e0 = e1 - __ldg(&g_cnt[w]);
    float dv = g_dinv[w];
    // self loop: xs[w] already carries dinv[w]; final *dv gives dinv^2
    float a = (sub == 0) ? __ldg(&g_xs[(size_t)w * 16 + c]) : 0.f;
    int k = e0 + sub;
    for (; k + 6 < e1; k += 8) {       // 4 edges per sub in flight
        int s0 = __ldg(&g_csr[k]);
        int s1 = __ldg(&g_csr[k + 2]);
        int s2 = __ldg(&g_csr[k + 4]);
        int s3 = __ldg(&g_csr[k + 6]);
        float v0 = __ldg(&g_xs[(size_t)s0 * 16 + c]);
        float v1 = __ldg(&g_xs[(size_t)s1 * 16 + c]);
        float v2 = __ldg(&g_xs[(size_t)s2 * 16 + c]);
        float v3 = __ldg(&g_xs[(size_t)s3 * 16 + c]);
        a += v0; a += v1; a += v2; a += v3;
    }
    for (; k < e1; k += 2) a += __ldg(&g_xs[(size_t)__ldg(&g_csr[k]) * 16 + c]);
    a *= dv;                                     // dinv[dst]
    a += __shfl_xor_sync(0xffffffffu, a, 16);    // combine subs; lane has a[lane&15]

    // mm 16 -> 64: lane computes cols {2*lane, 2*lane+1}
    float2 acc = sB[lane];
#pragma unroll
    for (int kk = 0; kk < 16; kk++) {
        float ak = __shfl_sync(0xffffffffu, a, kk);
        float2 wv = sW[kk * 32 + lane];
        acc.x = fmaf(ak, wv.x, acc.x);
        acc.y = fmaf(ak, wv.y, acc.y);
    }
    // pre-scale by dinv[w] for the next layer's aggregation
    __half2 hv = __floats2half2_rn(fmaxf(acc.x, 0.f) * dv, fmaxf(acc.y, 0.f) * dv);
    ((__half2*)g_h16a)[(size_t)w * 32 + lane] = hv;
}

// ---------------- 64-wide aggregation over pre-scaled fp16 -> bufa fp32 ------
template <int SRC>
__global__ void k_agg64() {
    const __half* __restrict__ h = (SRC == 0) ? g_h16a : g_h16b;
    int w = (blockIdx.x * 256 + threadIdx.x) >> 5;
    if (w >= N_NODES) return;
    int lane = threadIdx.x & 31;
    int sub = lane >> 4, t = lane & 15;
    int e1 = __ldg(&g_rowptr[w]);
    int e0 = e1 - __ldg(&g_cnt[w]);
    float dv = g_dinv[w];

    // self loop (features already dinv[w]-scaled; weight 1 in scaled space)
    float4 acc = make_float4(0.f, 0.f, 0.f, 0.f);
    if (sub == 0) {
        uint2 sv = __ldg((const uint2*)(h + (size_t)w * 64) + t);
        acc.x = h2f_lo(sv.x); acc.y = h2f_hi(sv.x);
        acc.z = h2f_lo(sv.y); acc.w = h2f_hi(sv.y);
    }

    int k = e0 + sub;
    for (; k + 6 < e1; k += 8) {       // 4 edges per sub: 4 csr + 4 feature loads in flight
        int s0 = __ldg(&g_csr[k]);
        int s1 = __ldg(&g_csr[k + 2]);
        int s2 = __ldg(&g_csr[k + 4]);
        int s3 = __ldg(&g_csr[k + 6]);
        uint2 f0 = __ldg((const uint2*)(h + (size_t)s0 * 64) + t);
        uint2 f1 = __ldg((const uint2*)(h + (size_t)s1 * 64) + t);
        uint2 f2 = __ldg((const uint2*)(h + (size_t)s2 * 64) + t);
        uint2 f3 = __ldg((const uint2*)(h + (size_t)s3 * 64) + t);
        acc.x += h2f_lo(f0.x); acc.y += h2f_hi(f0.x);
        acc.z += h2f_lo(f0.y); acc.w += h2f_hi(f0.y);
        acc.x += h2f_lo(f1.x); acc.y += h2f_hi(f1.x);
        acc.z += h2f_lo(f1.y); acc.w += h2f_hi(f1.y);
        acc.x += h2f_lo(f2.x); acc.y += h2f_hi(f2.x);
        acc.z += h2f_lo(f2.y); acc.w += h2f_hi(f2.y);
        acc.x += h2f_lo(f3.x); acc.y += h2f_hi(f3.x);
        acc.z += h2f_lo(f3.y); acc.w += h2f_hi(f3.y);
    }
    for (; k < e1; k += 2) {
        int s = __ldg(&g_csr[k]);
        uint2 f = __ldg((const uint2*)(h + (size_t)s * 64) + t);
        acc.x += h2f_lo(f.x); acc.y += h2f_hi(f.x);
        acc.z += h2f_lo(f.y); acc.w += h2f_hi(f.y);
    }
    // dinv[dst] + fp16-decode compensation, then combine halves
    float fs = dv * 0x1p112f;
    acc.x *= fs; acc.y *= fs; acc.z *= fs; acc.w *= fs;
    acc.x += __shfl_xor_sync(0xffffffffu, acc.x, 16);
    acc.y += __shfl_xor_sync(0xffffffffu, acc.y, 16);
    acc.z += __shfl_xor_sync(0xffffffffu, acc.z, 16);
    acc.w += __shfl_xor_sync(0xffffffffu, acc.w, 16);
    if (sub == 0) ((float4*)g_bufa)[(size_t)w * 16 + t] = acc;
}

// ---------------- matmul 64x64 + bias + relu: bufa -> fp16 buffer ------------
// SCALE=1: multiply rows by dinv[row] on output (feeds another aggregation).
template <int DST, int SCALE>
__global__ void k_mm64(const float* __restrict__ Wm, const float* __restrict__ bv) {
    __half* __restrict__ out = (DST == 0) ? g_h16a : g_h16b;
    __shared__ float4 sIn[64 * 16];
    __shared__ float sDv[64];
    int tid = threadIdx.x;           // 256
    int row0 = blockIdx.x * 64;
    int col = tid & 63;
    float wreg[64];
#pragma unroll
    for (int k = 0; k < 64; k++) wreg[k] = __ldg(&Wm[k * 64 + col]);
    float bias = __ldg(&bv[col]);
    int nrows = min(64, N_NODES - row0);
    for (int idx = tid; idx < nrows * 16; idx += 256)
        sIn[idx] = __ldg((const float4*)g_bufa + (size_t)row0 * 16 + idx);
    if (SCALE && tid < nrows) sDv[tid] = g_dinv[row0 + tid];
    __syncthreads();
    int rg = tid >> 6;
    for (int r = rg; r < nrows; r += 4) {
        float acc = bias;
#pragma unroll
        for (int k4 = 0; k4 < 16; k4++) {
            float4 v = sIn[r * 16 + k4];
            acc = fmaf(v.x, wreg[4 * k4 + 0], acc);
            acc = fmaf(v.y, wreg[4 * k4 + 1], acc);
            acc = fmaf(v.z, wreg[4 * k4 + 2], acc);
            acc = fmaf(v.w, wreg[4 * k4 + 3], acc);
        }
        acc = fmaxf(acc, 0.f);
        if (SCALE) acc *= sDv[r];
        out[(size_t)(row0 + r) * 64 + col] = __float2half_rn(acc);
    }
}

// ---------------- mean pool per graph (batch sorted); reads g_h16a -----------
__global__ void k_pool(const int* __restrict__ batch) {
    int g = blockIdx.x;
    int lo = 0, hi = N_NODES;
    while (lo < hi) { int mid = (lo + hi) >> 1; if (__ldg(&batch[mid]) < g) lo = mid + 1; else hi = mid; }
    int start = lo;
    lo = start; hi = N_NODES;
    while (lo < hi) { int mid = (lo + hi) >> 1; if (__ldg(&batch[mid]) < g + 1) lo = mid + 1; else hi = mid; }
    int end = lo;

    __shared__ float2 sp[8][32];
    int cp = threadIdx.x & 31, rg = threadIdx.x >> 5;
    float2 acc = make_float2(0.f, 0.f);
    const __half2* h2 = (const __half2*)g_h16a;
    for (int r = start + rg; r < end; r += 8) {
        float2 f = __half22float2(h2[(size_t)r * 32 + cp]);
        acc.x += f.x; acc.y += f.y;
    }
    sp[rg][cp] = acc;
    __syncthreads();
    if (rg == 0) {
        float2 t = sp[0][cp];
#pragma unroll
        for (int i = 1; i < 8; i++) { t.x += sp[i][cp].x; t.y += sp[i][cp].y; }
        float cnt = (float)(end - start);
        if (cnt < 1.f) cnt = 1.f;
        ((float2*)g_pool)[g * 32 + cp] = make_float2(t.x / cnt, t.y / cnt);
    }
}

// ---------------- MLP head ----------------
__global__ void k_head(const float* __restrict__ Wf1, const float* __restrict__ bf1,
                       const float* __restrict__ Wf2, const float* __restrict__ bf2,
                       float* __restrict__ out) {
    int g = threadIdx.x;
    if (g >= N_GRAPHS) return;
    float p[64];
#pragma unroll
    for (int k = 0; k < 64; k++) p[k] = g_pool[g * 64 + k];
    float o = __ldg(&bf2[0]);
#pragma unroll 4
    for (int j = 0; j < 32; j++) {
        float hj = __ldg(&bf1[j]);
#pragma unroll
        for (int k = 0; k < 64; k++) hj = fmaf(p[k], __ldg(&Wf1[k * 32 + j]), hj);
        o = fmaf(fmaxf(hj, 0.f), __ldg(&Wf2[j]), o);
    }
    out[g] = o;
}

// ---------------- launch ----------------
extern "C" void kernel_launch(void* const* d_in, const int* in_sizes, int n_in,
                              void* d_out, int out_size) {
    const float* x   = (const float*)d_in[0];
    const int*   ei  = (const int*)d_in[1];
    const int4*  src4 = (const int4*)ei;
    const int4*  dst4 = (const int4*)(ei + N_EDGES);
    const int*   batch = (const int*)d_in[3];
    const float* W1 = (const float*)d_in[4];  const float* b1 = (const float*)d_in[5];
    const float* W2 = (const float*)d_in[6];  const float* b2 = (const float*)d_in[7];
    const float* W3 = (const float*)d_in[8];  const float* b3 = (const float*)d_in[9];
    const float* Wf1 = (const float*)d_in[10]; const float* bf1 = (const float*)d_in[11];
    const float* Wf2 = (const float*)d_in[12]; const float* bf2 = (const float*)d_in[13];
    float* out = (float*)d_out;

    const int nb_scan = (N_NODES + 1023) / 1024;       // 98
    const int eb4 = (N_EDGES / 4) / 256;               // 3125
    const int wb = (N_NODES * 32 + 255) / 256;         // one warp per node: 12500
    const int mb = (N_NODES + 63) / 64;                // 1563

    k_zero_cnt<<<(N_NODES + 255) / 256, 256>>>();
    k_hist<<<eb4, 256>>>(dst4);
    k_scan_blocks<<<nb_scan, 1024>>>();
    k_scan_add<<<nb_scan, 1024>>>(x);
    k_fill<<<eb4, 256>>>(src4, dst4);

    k_agg16_mm1<<<wb, 256>>>(W1, b1);          // layer 1 fused -> h16a (scaled)
    k_agg64<0><<<wb, 256>>>();                 // gather h16a -> bufa
    k_mm64<1, 1><<<mb, 256>>>(W2, b2);         // bufa@W2 -> h16b (scaled)
    k_agg64<1><<<wb, 256>>>();                 // gather h16b -> bufa
    k_mm64<0, 0><<<mb, 256>>>(W3, b3);         // bufa@W3 -> h16a (raw, for pool)

    k_pool<<<N_GRAPHS, 256>>>(batch);
    k_head<<<1, 128>>>(Wf1, bf1, Wf2, bf2, out);
}

// round 8
// speedup vs baseline: 1.2926x; 1.0380x over previous
#include <cuda_runtime.h>
#include <cuda_fp16.h>

#define N_NODES  100000
#define N_EDGES  3200000
#define N_GRAPHS 128

// ---------------- scratch (static device globals; no runtime alloc) ----------
__device__ int   g_cnt[N_NODES];
__device__ int   g_rowptr[N_NODES];            // after k_fill: END of each row
__device__ int   g_bsums[128];
__device__ int   g_done;                       // pool->head ticket (zeroed each launch)
__device__ float g_dinv[N_NODES];
__device__ int   g_csr[N_EDGES];               // src only (features pre-scaled by dinv)
__device__ __align__(16) float g_xs[N_NODES * 16];     // x * dinv[node]
__device__ __align__(16) __half g_aggh[N_NODES * 64];  // aggregation output (fp16)
__device__ __align__(16) __half g_h16a[N_NODES * 64];  // activations fp16 (L1 scaled, L3 raw)
__device__ __align__(16) __half g_h16b[N_NODES * 64];  // activations fp16 (L2 scaled)
__device__ __align__(16) float g_pool[N_GRAPHS * 64];

// half(nonneg)->float bit tricks; result is 2^-112 * true_value; compensated once
// per node (exact incl. subnormals; activations are post-ReLU so sign bit is 0).
__device__ __forceinline__ float h2f_lo(unsigned v) { return __int_as_float((v & 0xffffu) << 13); }
__device__ __forceinline__ float h2f_hi(unsigned v) { return __int_as_float((v >> 3) & 0x1FFFE000u); }

// ---------------- degree histogram ----------------
__global__ void k_zero_cnt() {
    int i = blockIdx.x * blockDim.x + threadIdx.x;
    if (i < N_NODES) g_cnt[i] = 0;
    if (i == 0) g_done = 0;
}

__global__ void k_hist(const int4* __restrict__ dst4) {
    int i = blockIdx.x * blockDim.x + threadIdx.x;   // N_EDGES/4 threads
    int4 d = __ldg(&dst4[i]);
    atomicAdd(&g_cnt[d.x], 1);
    atomicAdd(&g_cnt[d.y], 1);
    atomicAdd(&g_cnt[d.z], 1);
    atomicAdd(&g_cnt[d.w], 1);
}

// ---------------- exclusive scan over 100k counts (2 kernels) ----------------
__global__ void k_scan_blocks() {
    __shared__ int s[1024];
    int tid = threadIdx.x;
    int i = blockIdx.x * 1024 + tid;
    int v = (i < N_NODES) ? g_cnt[i] : 0;
    s[tid] = v;
    __syncthreads();
    for (int off = 1; off < 1024; off <<= 1) {
        int t = (tid >= off) ? s[tid - off] : 0;
        __syncthreads();
        s[tid] += t;
        __syncthreads();
    }
    if (i < N_NODES) g_rowptr[i] = s[tid] - v;   // exclusive within block
    if (tid == 1023) g_bsums[blockIdx.x] = s[1023];
}

// scan finish + dinv + pre-scaled x (fused; no extra launch)
__global__ void k_scan_add(const float* __restrict__ x) {
    __shared__ int s_pre;
    int tid = threadIdx.x;
    if (tid < 32) {
        int acc = 0;
        for (int b = tid; b < blockIdx.x; b += 32) acc += g_bsums[b];
        for (int off = 16; off > 0; off >>= 1) acc += __shfl_xor_sync(0xffffffffu, acc, off);
        if (tid == 0) s_pre = acc;
    }
    __syncthreads();
    int i = blockIdx.x * 1024 + tid;
    if (i < N_NODES) {
        g_rowptr[i] += s_pre;
        float dv = rsqrtf((float)(g_cnt[i] + 1));   // +1 self loop
        g_dinv[i] = dv;
        const float4* xr = (const float4*)(x + (size_t)i * 16);
        float4* xo = (float4*)(g_xs + (size_t)i * 16);
#pragma unroll
        for (int c = 0; c < 4; c++) {
            float4 v = __ldg(&xr[c]);
            v.x *= dv; v.y *= dv; v.z *= dv; v.w *= dv;
            xo[c] = v;
        }
    }
}

// ---------------- CSR fill: rowptr itself is the cursor (becomes row END) ----
__global__ void k_fill(const int4* __restrict__ src4, const int4* __restrict__ dst4) {
    int i = blockIdx.x * blockDim.x + threadIdx.x;   // N_EDGES/4 threads
    int4 s = __ldg(&src4[i]);
    int4 d = __ldg(&dst4[i]);
    g_csr[atomicAdd(&g_rowptr[d.x], 1)] = s.x;
    g_csr[atomicAdd(&g_rowptr[d.y], 1)] = s.y;
    g_csr[atomicAdd(&g_rowptr[d.z], 1)] = s.z;
    g_csr[atomicAdd(&g_rowptr[d.w], 1)] = s.w;
}

// ---------------- layer 1 fused: agg(xs,16) then @W1[16,64]+b1, relu --------
// writes h16a PRE-SCALED by dinv[w] for layer-2 consumption.
__global__ void k_agg16_mm1(const float* __restrict__ W1, const float* __restrict__ b1) {
    __shared__ float2 sW[16 * 32];
    __shared__ float2 sB[32];
    int tid = threadIdx.x;
    for (int idx = tid; idx < 16 * 32; idx += 256) sW[idx] = __ldg((const float2*)W1 + idx);
    if (tid < 32) sB[tid] = __ldg((const float2*)b1 + tid);
    __syncthreads();

    int w = (blockIdx.x * 256 + tid) >> 5;
    if (w >= N_NODES) return;
    int lane = tid & 31;
    int sub = lane >> 4, c = lane & 15;
    int e1 = __ldg(&g_rowptr[w]);
    int e0 = e1 - __ldg(&g_cnt[w]);
    float dv = g_dinv[w];
    // self loop: xs[w] already carries dinv[w]; final *dv gives dinv^2
    float a = (sub == 0) ? __ldg(&g_xs[(size_t)w * 16 + c]) : 0.f;
    int k = e0 + sub;
    for (; k + 6 < e1; k += 8) {       // 4 edges per sub in flight
        int s0 = __ldg(&g_csr[k]);
        int s1 = __ldg(&g_csr[k + 2]);
        int s2 = __ldg(&g_csr[k + 4]);
        int s3 = __ldg(&g_csr[k + 6]);
        float v0 = __ldg(&g_xs[(size_t)s0 * 16 + c]);
        float v1 = __ldg(&g_xs[(size_t)s1 * 16 + c]);
        float v2 = __ldg(&g_xs[(size_t)s2 * 16 + c]);
        float v3 = __ldg(&g_xs[(size_t)s3 * 16 + c]);
        a += v0; a += v1; a += v2; a += v3;
    }
    for (; k < e1; k += 2) a += __ldg(&g_xs[(size_t)__ldg(&g_csr[k]) * 16 + c]);
    a *= dv;                                     // dinv[dst]
    a += __shfl_xor_sync(0xffffffffu, a, 16);    // combine subs; lane has a[lane&15]

    // mm 16 -> 64: lane computes cols {2*lane, 2*lane+1}
    float2 acc = sB[lane];
#pragma unroll
    for (int kk = 0; kk < 16; kk++) {
        float ak = __shfl_sync(0xffffffffu, a, kk);
        float2 wv = sW[kk * 32 + lane];
        acc.x = fmaf(ak, wv.x, acc.x);
        acc.y = fmaf(ak, wv.y, acc.y);
    }
    // pre-scale by dinv[w] for the next layer's aggregation
    __half2 hv = __floats2half2_rn(fmaxf(acc.x, 0.f) * dv, fmaxf(acc.y, 0.f) * dv);
    ((__half2*)g_h16a)[(size_t)w * 32 + lane] = hv;
}

// ---------------- 64-wide aggregation over pre-scaled fp16 -> g_aggh fp16 ----
template <int SRC>
__global__ void k_agg64() {
    const __half* __restrict__ h = (SRC == 0) ? g_h16a : g_h16b;
    int w = (blockIdx.x * 256 + threadIdx.x) >> 5;
    if (w >= N_NODES) return;
    int lane = threadIdx.x & 31;
    int sub = lane >> 4, t = lane & 15;
    int e1 = __ldg(&g_rowptr[w]);
    int e0 = e1 - __ldg(&g_cnt[w]);
    float dv = g_dinv[w];

    // self loop (features already dinv[w]-scaled; weight 1 in scaled space)
    float4 acc = make_float4(0.f, 0.f, 0.f, 0.f);
    if (sub == 0) {
        uint2 sv = __ldg((const uint2*)(h + (size_t)w * 64) + t);
        acc.x = h2f_lo(sv.x); acc.y = h2f_hi(sv.x);
        acc.z = h2f_lo(sv.y); acc.w = h2f_hi(sv.y);
    }

    int k = e0 + sub;
    for (; k + 14 < e1; k += 16) {     // 8 edges per sub: 8 csr + 8 feature loads in flight
        int s0 = __ldg(&g_csr[k]);
        int s1 = __ldg(&g_csr[k + 2]);
        int s2 = __ldg(&g_csr[k + 4]);
        int s3 = __ldg(&g_csr[k + 6]);
        int s4 = __ldg(&g_csr[k + 8]);
        int s5 = __ldg(&g_csr[k + 10]);
        int s6 = __ldg(&g_csr[k + 12]);
        int s7 = __ldg(&g_csr[k + 14]);
        uint2 f0 = __ldg((const uint2*)(h + (size_t)s0 * 64) + t);
        uint2 f1 = __ldg((const uint2*)(h + (size_t)s1 * 64) + t);
        uint2 f2 = __ldg((const uint2*)(h + (size_t)s2 * 64) + t);
        uint2 f3 = __ldg((const uint2*)(h + (size_t)s3 * 64) + t);
        uint2 f4 = __ldg((const uint2*)(h + (size_t)s4 * 64) + t);
        uint2 f5 = __ldg((const uint2*)(h + (size_t)s5 * 64) + t);
        uint2 f6 = __ldg((const uint2*)(h + (size_t)s6 * 64) + t);
        uint2 f7 = __ldg((const uint2*)(h + (size_t)s7 * 64) + t);
        acc.x += h2f_lo(f0.x); acc.y += h2f_hi(f0.x);
        acc.z += h2f_lo(f0.y); acc.w += h2f_hi(f0.y);
        acc.x += h2f_lo(f1.x); acc.y += h2f_hi(f1.x);
        acc.z += h2f_lo(f1.y); acc.w += h2f_hi(f1.y);
        acc.x += h2f_lo(f2.x); acc.y += h2f_hi(f2.x);
        acc.z += h2f_lo(f2.y); acc.w += h2f_hi(f2.y);
        acc.x += h2f_lo(f3.x); acc.y += h2f_hi(f3.x);
        acc.z += h2f_lo(f3.y); acc.w += h2f_hi(f3.y);
        acc.x += h2f_lo(f4.x); acc.y += h2f_hi(f4.x);
        acc.z += h2f_lo(f4.y); acc.w += h2f_hi(f4.y);
        acc.x += h2f_lo(f5.x); acc.y += h2f_hi(f5.x);
        acc.z += h2f_lo(f5.y); acc.w += h2f_hi(f5.y);
        acc.x += h2f_lo(f6.x); acc.y += h2f_hi(f6.x);
        acc.z += h2f_lo(f6.y); acc.w += h2f_hi(f6.y);
        acc.x += h2f_lo(f7.x); acc.y += h2f_hi(f7.x);
        acc.z += h2f_lo(f7.y); acc.w += h2f_hi(f7.y);
    }
    for (; k + 6 < e1; k += 8) {       // 4 edges per sub
        int s0 = __ldg(&g_csr[k]);
        int s1 = __ldg(&g_csr[k + 2]);
        int s2 = __ldg(&g_csr[k + 4]);
        int s3 = __ldg(&g_csr[k + 6]);
        uint2 f0 = __ldg((const uint2*)(h + (size_t)s0 * 64) + t);
        uint2 f1 = __ldg((const uint2*)(h + (size_t)s1 * 64) + t);
        uint2 f2 = __ldg((const uint2*)(h + (size_t)s2 * 64) + t);
        uint2 f3 = __ldg((const uint2*)(h + (size_t)s3 * 64) + t);
        acc.x += h2f_lo(f0.x); acc.y += h2f_hi(f0.x);
        acc.z += h2f_lo(f0.y); acc.w += h2f_hi(f0.y);
        acc.x += h2f_lo(f1.x); acc.y += h2f_hi(f1.x);
        acc.z += h2f_lo(f1.y); acc.w += h2f_hi(f1.y);
        acc.x += h2f_lo(f2.x); acc.y += h2f_hi(f2.x);
        acc.z += h2f_lo(f2.y); acc.w += h2f_hi(f2.y);
        acc.x += h2f_lo(f3.x); acc.y += h2f_hi(f3.x);
        acc.z += h2f_lo(f3.y); acc.w += h2f_hi(f3.y);
    }
    for (; k < e1; k += 2) {
        int s = __ldg(&g_csr[k]);
        uint2 f = __ldg((const uint2*)(h + (size_t)s * 64) + t);
        acc.x += h2f_lo(f.x); acc.y += h2f_hi(f.x);
        acc.z += h2f_lo(f.y); acc.w += h2f_hi(f.y);
    }
    // dinv[dst] + fp16-decode compensation, then combine halves
    float fs = dv * 0x1p112f;
    acc.x *= fs; acc.y *= fs; acc.z *= fs; acc.w *= fs;
    acc.x += __shfl_xor_sync(0xffffffffu, acc.x, 16);
    acc.y += __shfl_xor_sync(0xffffffffu, acc.y, 16);
    acc.z += __shfl_xor_sync(0xffffffffu, acc.z, 16);
    acc.w += __shfl_xor_sync(0xffffffffu, acc.w, 16);
    if (sub == 0) {
        __half2 h0 = __floats2half2_rn(acc.x, acc.y);
        __half2 h1 = __floats2half2_rn(acc.z, acc.w);
        uint2 st;
        st.x = *(unsigned*)&h0;
        st.y = *(unsigned*)&h1;
        ((uint2*)(g_aggh + (size_t)w * 64))[t] = st;
    }
}

// ---------------- matmul 64x64 + bias + relu: g_aggh (fp16) -> fp16 buffer ---
// SCALE=1: multiply rows by dinv[row] on output (feeds another aggregation).
template <int DST, int SCALE>
__global__ void k_mm64(const float* __restrict__ Wm, const float* __restrict__ bv) {
    __half* __restrict__ out = (DST == 0) ? g_h16a : g_h16b;
    __shared__ float4 sIn[64 * 16];
    __shared__ float sDv[64];
    int tid = threadIdx.x;           // 256
    int row0 = blockIdx.x * 64;
    int col = tid & 63;
    float wreg[64];
#pragma unroll
    for (int k = 0; k < 64; k++) wreg[k] = __ldg(&Wm[k * 64 + col]);
    float bias = __ldg(&bv[col]);
    int nrows = min(64, N_NODES - row0);
    // stage fp16 -> fp32 (16 halves per uint4 iter is overkill; do 4 per uint2)
    for (int idx = tid; idx < nrows * 16; idx += 256) {
        uint2 v = __ldg((const uint2*)(g_aggh + (size_t)row0 * 64) + idx);
        float2 a = __half22float2(*(__half2*)&v.x);
        float2 b = __half22float2(*(__half2*)&v.y);
        sIn[idx] = make_float4(a.x, a.y, b.x, b.y);
    }
    if (SCALE && tid < nrows) sDv[tid] = g_dinv[row0 + tid];
    __syncthreads();
    int rg = tid >> 6;
    for (int r = rg; r < nrows; r += 4) {
        float acc = bias;
#pragma unroll
        for (int k4 = 0; k4 < 16; k4++) {
            float4 v = sIn[r * 16 + k4];
            acc = fmaf(v.x, wreg[4 * k4 + 0], acc);
            acc = fmaf(v.y, wreg[4 * k4 + 1], acc);
            acc = fmaf(v.z, wreg[4 * k4 + 2], acc);
            acc = fmaf(v.w, wreg[4 * k4 + 3], acc);
        }
        acc = fmaxf(acc, 0.f);
        if (SCALE) acc *= sDv[r];
        out[(size_t)(row0 + r) * 64 + col] = __float2half_rn(acc);
    }
}

// ---------------- fused mean pool + MLP head (last block does the head) ------
__global__ void k_pool_head(const int* __restrict__ batch,
                            const float* __restrict__ Wf1, const float* __restrict__ bf1,
                            const float* __restrict__ Wf2, const float* __restrict__ bf2,
                            float* __restrict__ out) {
    int g = blockIdx.x;
    int lo = 0, hi = N_NODES;
    while (lo < hi) { int mid = (lo + hi) >> 1; if (__ldg(&batch[mid]) < g) lo = mid + 1; else hi = mid; }
    int start = lo;
    lo = start; hi = N_NODES;
    while (lo < hi) { int mid = (lo + hi) >> 1; if (__ldg(&batch[mid]) < g + 1) lo = mid + 1; else hi = mid; }
    int end = lo;

    __shared__ float2 sp[8][32];
    int cp = threadIdx.x & 31, rg = threadIdx.x >> 5;
    float2 acc = make_float2(0.f, 0.f);
    const __half2* h2 = (const __half2*)g_h16a;
    for (int r = start + rg; r < end; r += 8) {
        float2 f = __half22float2(h2[(size_t)r * 32 + cp]);
        acc.x += f.x; acc.y += f.y;
    }
    sp[rg][cp] = acc;
    __syncthreads();
    if (rg == 0) {
        float2 t = sp[0][cp];
#pragma unroll
        for (int i = 1; i < 8; i++) { t.x += sp[i][cp].x; t.y += sp[i][cp].y; }
        float cnt = (float)(end - start);
        if (cnt < 1.f) cnt = 1.f;
        ((float2*)g_pool)[g * 32 + cp] = make_float2(t.x / cnt, t.y / cnt);
    }

    // last block to finish runs the head
    __shared__ int s_last;
    __threadfence();
    __syncthreads();
    if (threadIdx.x == 0) s_last = (atomicAdd(&g_done, 1) == N_GRAPHS - 1);
    __syncthreads();
    if (!s_last) return;
    __threadfence();

    int gg = threadIdx.x;
    if (gg >= N_GRAPHS) return;
    float p[64];
#pragma unroll
    for (int k = 0; k < 64; k++) p[k] = g_pool[gg * 64 + k];
    float o = __ldg(&bf2[0]);
#pragma unroll 4
    for (int j = 0; j < 32; j++) {
        float hj = __ldg(&bf1[j]);
#pragma unroll
        for (int k = 0; k < 64; k++) hj = fmaf(p[k], __ldg(&Wf1[k * 32 + j]), hj);
        o = fmaf(fmaxf(hj, 0.f), __ldg(&Wf2[j]), o);
    }
    out[gg] = o;
}

// ---------------- launch ----------------
extern "C" void kernel_launch(void* const* d_in, const int* in_sizes, int n_in,
                              void* d_out, int out_size) {
    const float* x   = (const float*)d_in[0];
    const int*   ei  = (const int*)d_in[1];
    const int4*  src4 = (const int4*)ei;
    const int4*  dst4 = (const int4*)(ei + N_EDGES);
    const int*   batch = (const int*)d_in[3];
    const float* W1 = (const float*)d_in[4];  const float* b1 = (const float*)d_in[5];
    const float* W2 = (const float*)d_in[6];  const float* b2 = (const float*)d_in[7];
    const float* W3 = (const float*)d_in[8];  const float* b3 = (const float*)d_in[9];
    const float* Wf1 = (const float*)d_in[10]; const float* bf1 = (const float*)d_in[11];
    const float* Wf2 = (const float*)d_in[12]; const float* bf2 = (const float*)d_in[13];
    float* out = (float*)d_out;

    const int nb_scan = (N_NODES + 1023) / 1024;       // 98
    const int eb4 = (N_EDGES / 4) / 256;               // 3125
    const int wb = (N_NODES * 32 + 255) / 256;         // one warp per node: 12500
    const int mb = (N_NODES + 63) / 64;                // 1563

    k_zero_cnt<<<(N_NODES + 255) / 256, 256>>>();
    k_hist<<<eb4, 256>>>(dst4);
    k_scan_blocks<<<nb_scan, 1024>>>();
    k_scan_add<<<nb_scan, 1024>>>(x);
    k_fill<<<eb4, 256>>>(src4, dst4);

    k_agg16_mm1<<<wb, 256>>>(W1, b1);          // layer 1 fused -> h16a (scaled)
    k_agg64<0><<<wb, 256>>>();                 // gather h16a -> aggh (fp16)
    k_mm64<1, 1><<<mb, 256>>>(W2, b2);         // aggh@W2 -> h16b (scaled)
    k_agg64<1><<<wb, 256>>>();                 // gather h16b -> aggh (fp16)
    k_mm64<0, 0><<<mb, 256>>>(W3, b3);         // aggh@W3 -> h16a (raw, for pool)

    k_pool_head<<<N_GRAPHS, 256>>>(batch, Wf1, bf1, Wf2, bf2, out);
}

// round 9
// speedup vs baseline: 1.3316x; 1.0301x over previous
#include <cuda_runtime.h>

#define N_NODES  100000
#define N_EDGES  3200000
#define N_GRAPHS 128

// ---------------- scratch (static device globals; no runtime alloc) ----------
__device__ int   g_cnt[N_NODES];
__device__ int   g_rowptr[N_NODES];            // after k_fill: END of each row
__device__ int   g_bsums[128];
__device__ int   g_done;                       // pool->head ticket (zeroed each launch)
__device__ float g_dinv[N_NODES];
__device__ int   g_csr[N_EDGES];               // src only (features pre-scaled by dinv)
__device__ __align__(16) unsigned g_xs[N_NODES * 8];    // x*dinv as bf16 pairs
__device__ __align__(16) unsigned g_aggu[N_NODES * 32]; // aggregation output (bf16 pairs)
__device__ __align__(16) unsigned g_ha[N_NODES * 32];   // activations bf16 (L1 scaled, L3 raw)
__device__ __align__(16) unsigned g_hb[N_NODES * 32];   // activations bf16 (L2 scaled)
__device__ __align__(16) float g_pool[N_GRAPHS * 64];

// bf16 pair decode: EXACT (bf16 is fp32 with truncated mantissa). 1 instr each.
__device__ __forceinline__ float bf_lo(unsigned v) { return __int_as_float(v << 16); }
__device__ __forceinline__ float bf_hi(unsigned v) { return __int_as_float(v & 0xffff0000u); }
// pack two floats into a bf16 pair (lo = first/even column), single instruction
__device__ __forceinline__ unsigned bf2_pack(float lo, float hi) {
    unsigned r;
    asm("cvt.rn.bf16x2.f32 %0, %1, %2;" : "=r"(r) : "f"(hi), "f"(lo));
    return r;
}

// ---------------- degree histogram ----------------
__global__ void k_zero_cnt() {
    int i = blockIdx.x * blockDim.x + threadIdx.x;
    if (i < N_NODES) g_cnt[i] = 0;
    if (i == 0) g_done = 0;
}

__global__ void k_hist(const int4* __restrict__ dst4) {
    int i = blockIdx.x * blockDim.x + threadIdx.x;   // N_EDGES/4 threads
    int4 d = __ldg(&dst4[i]);
    atomicAdd(&g_cnt[d.x], 1);
    atomicAdd(&g_cnt[d.y], 1);
    atomicAdd(&g_cnt[d.z], 1);
    atomicAdd(&g_cnt[d.w], 1);
}

// ---------------- exclusive scan over 100k counts (2 kernels) ----------------
__global__ void k_scan_blocks() {
    __shared__ int s[1024];
    int tid = threadIdx.x;
    int i = blockIdx.x * 1024 + tid;
    int v = (i < N_NODES) ? g_cnt[i] : 0;
    s[tid] = v;
    __syncthreads();
    for (int off = 1; off < 1024; off <<= 1) {
        int t = (tid >= off) ? s[tid - off] : 0;
        __syncthreads();
        s[tid] += t;
        __syncthreads();
    }
    if (i < N_NODES) g_rowptr[i] = s[tid] - v;   // exclusive within block
    if (tid == 1023) g_bsums[blockIdx.x] = s[1023];
}

// scan finish + dinv + pre-scaled bf16 x (fused)
__global__ void k_scan_add(const float* __restrict__ x) {
    __shared__ int s_pre;
    int tid = threadIdx.x;
    if (tid < 32) {
        int acc = 0;
        for (int b = tid; b < blockIdx.x; b += 32) acc += g_bsums[b];
        for (int off = 16; off > 0; off >>= 1) acc += __shfl_xor_sync(0xffffffffu, acc, off);
        if (tid == 0) s_pre = acc;
    }
    __syncthreads();
    int i = blockIdx.x * 1024 + tid;
    if (i < N_NODES) {
        g_rowptr[i] += s_pre;
        float dv = rsqrtf((float)(g_cnt[i] + 1));   // +1 self loop
        g_dinv[i] = dv;
        const float4* xr = (const float4*)(x + (size_t)i * 16);
        uint4* xo = (uint4*)(g_xs + (size_t)i * 8);
#pragma unroll
        for (int c = 0; c < 2; c++) {
            float4 v0 = __ldg(&xr[2 * c]);
            float4 v1 = __ldg(&xr[2 * c + 1]);
            uint4 u;
            u.x = bf2_pack(v0.x * dv, v0.y * dv);
            u.y = bf2_pack(v0.z * dv, v0.w * dv);
            u.z = bf2_pack(v1.x * dv, v1.y * dv);
            u.w = bf2_pack(v1.z * dv, v1.w * dv);
            xo[c] = u;
        }
    }
}

// ---------------- CSR fill: rowptr itself is the cursor (becomes row END) ----
__global__ void k_fill(const int4* __restrict__ src4, const int4* __restrict__ dst4) {
    int i = blockIdx.x * blockDim.x + threadIdx.x;   // N_EDGES/4 threads
    int4 s = __ldg(&src4[i]);
    int4 d = __ldg(&dst4[i]);
    g_csr[atomicAdd(&g_rowptr[d.x], 1)] = s.x;
    g_csr[atomicAdd(&g_rowptr[d.y], 1)] = s.y;
    g_csr[atomicAdd(&g_rowptr[d.z], 1)] = s.z;
    g_csr[atomicAdd(&g_rowptr[d.w], 1)] = s.w;
}

// ---------------- layer 1 fused: agg(xs,16) then @W1[16,64]+b1, relu --------
// warp per node; 4 subs of 8 lanes, sub handles every-4th edge; lane = col pair.
// writes g_ha PRE-SCALED by dinv[w] for layer-2 consumption.
__global__ void k_agg16_mm1(const float* __restrict__ W1, const float* __restrict__ b1) {
    __shared__ float2 sW[16 * 32];
    __shared__ float2 sB[32];
    int tid = threadIdx.x;
    for (int idx = tid; idx < 16 * 32; idx += 256) sW[idx] = __ldg((const float2*)W1 + idx);
    if (tid < 32) sB[tid] = __ldg((const float2*)b1 + tid);
    __syncthreads();

    int w = (blockIdx.x * 256 + tid) >> 5;
    if (w >= N_NODES) return;
    int lane = tid & 31;
    int sub = lane >> 3, c2 = lane & 7;     // c2 covers cols {2c2, 2c2+1}
    int e1 = __ldg(&g_rowptr[w]);
    int e0 = e1 - __ldg(&g_cnt[w]);
    float2 a = make_float2(0.f, 0.f);
    float dv = g_dinv[w];
    if (sub == 0) {                          // self loop (xs already dinv-scaled)
        unsigned u = __ldg(&g_xs[(size_t)w * 8 + c2]);
        a.x = bf_lo(u); a.y = bf_hi(u);
    }
    int k = e0 + sub;
    for (; k + 12 < e1; k += 16) {           // 4 edges per sub in flight (16/warp)
        int s0 = __ldg(&g_csr[k]);
        int s1 = __ldg(&g_csr[k + 4]);
        int s2 = __ldg(&g_csr[k + 8]);
        int s3 = __ldg(&g_csr[k + 12]);
        unsigned u0 = __ldg(&g_xs[(size_t)s0 * 8 + c2]);
        unsigned u1 = __ldg(&g_xs[(size_t)s1 * 8 + c2]);
        unsigned u2 = __ldg(&g_xs[(size_t)s2 * 8 + c2]);
        unsigned u3 = __ldg(&g_xs[(size_t)s3 * 8 + c2]);
        a.x += bf_lo(u0); a.y += bf_hi(u0);
        a.x += bf_lo(u1); a.y += bf_hi(u1);
        a.x += bf_lo(u2); a.y += bf_hi(u2);
        a.x += bf_lo(u3); a.y += bf_hi(u3);
    }
    for (; k < e1; k += 4) {
        unsigned u = __ldg(&g_xs[(size_t)__ldg(&g_csr[k]) * 8 + c2]);
        a.x += bf_lo(u); a.y += bf_hi(u);
    }
    a.x *= dv; a.y *= dv;                    // dinv[dst]
    // combine 4 subs
    a.x += __shfl_xor_sync(0xffffffffu, a.x, 8);
    a.y += __shfl_xor_sync(0xffffffffu, a.y, 8);
    a.x += __shfl_xor_sync(0xffffffffu, a.x, 16);
    a.y += __shfl_xor_sync(0xffffffffu, a.y, 16);
    // lane j (j<8) holds agg cols {2j, 2j+1}; replicated in all lanes

    // mm 16 -> 64: lane computes cols {2*lane, 2*lane+1}
    float2 acc = sB[lane];
#pragma unroll
    for (int kk = 0; kk < 16; kk++) {
        float ak = __shfl_sync(0xffffffffu, (kk & 1) ? a.y : a.x, kk >> 1);
        float2 wv = sW[kk * 32 + lane];
        acc.x = fmaf(ak, wv.x, acc.x);
        acc.y = fmaf(ak, wv.y, acc.y);
    }
    // pre-scale by dinv[w] for next layer's aggregation
    g_ha[(size_t)w * 32 + lane] = bf2_pack(fmaxf(acc.x, 0.f) * dv, fmaxf(acc.y, 0.f) * dv);
}

// ---------------- 64-wide aggregation over pre-scaled bf16 -> g_aggu ---------
template <int SRC>
__global__ void k_agg64() {
    const unsigned* __restrict__ h = (SRC == 0) ? g_ha : g_hb;
    int w = (blockIdx.x * 256 + threadIdx.x) >> 5;
    if (w >= N_NODES) return;
    int lane = threadIdx.x & 31;
    int sub = lane >> 4, t = lane & 15;      // t covers cols {4t..4t+3}
    int e1 = __ldg(&g_rowptr[w]);
    int e0 = e1 - __ldg(&g_cnt[w]);
    float dv = g_dinv[w];

    float4 acc = make_float4(0.f, 0.f, 0.f, 0.f);
    if (sub == 0) {                          // self loop
        uint2 sv = __ldg((const uint2*)(h + (size_t)w * 32) + t);
        acc.x = bf_lo(sv.x); acc.y = bf_hi(sv.x);
        acc.z = bf_lo(sv.y); acc.w = bf_hi(sv.y);
    }

    int k = e0 + sub;
    for (; k + 14 < e1; k += 16) {           // 8 edges per sub in flight
        int s0 = __ldg(&g_csr[k]);
        int s1 = __ldg(&g_csr[k + 2]);
        int s2 = __ldg(&g_csr[k + 4]);
        int s3 = __ldg(&g_csr[k + 6]);
        int s4 = __ldg(&g_csr[k + 8]);
        int s5 = __ldg(&g_csr[k + 10]);
        int s6 = __ldg(&g_csr[k + 12]);
        int s7 = __ldg(&g_csr[k + 14]);
        uint2 f0 = __ldg((const uint2*)(h + (size_t)s0 * 32) + t);
        uint2 f1 = __ldg((const uint2*)(h + (size_t)s1 * 32) + t);
        uint2 f2 = __ldg((const uint2*)(h + (size_t)s2 * 32) + t);
        uint2 f3 = __ldg((const uint2*)(h + (size_t)s3 * 32) + t);
        uint2 f4 = __ldg((const uint2*)(h + (size_t)s4 * 32) + t);
        uint2 f5 = __ldg((const uint2*)(h + (size_t)s5 * 32) + t);
        uint2 f6 = __ldg((const uint2*)(h + (size_t)s6 * 32) + t);
        uint2 f7 = __ldg((const uint2*)(h + (size_t)s7 * 32) + t);
        acc.x += bf_lo(f0.x); acc.y += bf_hi(f0.x);
        acc.z += bf_lo(f0.y); acc.w += bf_hi(f0.y);
        acc.x += bf_lo(f1.x); acc.y += bf_hi(f1.x);
        acc.z += bf_lo(f1.y); acc.w += bf_hi(f1.y);
        acc.x += bf_lo(f2.x); acc.y += bf_hi(f2.x);
        acc.z += bf_lo(f2.y); acc.w += bf_hi(f2.y);
        acc.x += bf_lo(f3.x); acc.y += bf_hi(f3.x);
        acc.z += bf_lo(f3.y); acc.w += bf_hi(f3.y);
        acc.x += bf_lo(f4.x); acc.y += bf_hi(f4.x);
        acc.z += bf_lo(f4.y); acc.w += bf_hi(f4.y);
        acc.x += bf_lo(f5.x); acc.y += bf_hi(f5.x);
        acc.z += bf_lo(f5.y); acc.w += bf_hi(f5.y);
        acc.x += bf_lo(f6.x); acc.y += bf_hi(f6.x);
        acc.z += bf_lo(f6.y); acc.w += bf_hi(f6.y);
        acc.x += bf_lo(f7.x); acc.y += bf_hi(f7.x);
        acc.z += bf_lo(f7.y); acc.w += bf_hi(f7.y);
    }
    for (; k < e1; k += 2) {
        int s = __ldg(&g_csr[k]);
        uint2 f = __ldg((const uint2*)(h + (size_t)s * 32) + t);
        acc.x += bf_lo(f.x); acc.y += bf_hi(f.x);
        acc.z += bf_lo(f.y); acc.w += bf_hi(f.y);
    }
    // dinv[dst], then combine the two halves
    acc.x *= dv; acc.y *= dv; acc.z *= dv; acc.w *= dv;
    acc.x += __shfl_xor_sync(0xffffffffu, acc.x, 16);
    acc.y += __shfl_xor_sync(0xffffffffu, acc.y, 16);
    acc.z += __shfl_xor_sync(0xffffffffu, acc.z, 16);
    acc.w += __shfl_xor_sync(0xffffffffu, acc.w, 16);
    if (sub == 0) {
        uint2 st;
        st.x = bf2_pack(acc.x, acc.y);
        st.y = bf2_pack(acc.z, acc.w);
        ((uint2*)(g_aggu + (size_t)w * 32))[t] = st;
    }
}

// ---------------- matmul 64x64 + bias + relu: g_aggu (bf16) -> bf16 buffer ---
// SCALE=1: multiply rows by dinv[row] on output (feeds another aggregation).
template <int DST, int SCALE>
__global__ void k_mm64(const float* __restrict__ Wm, const float* __restrict__ bv) {
    unsigned* __restrict__ out = (DST == 0) ? g_ha : g_hb;
    __shared__ float4 sIn[64 * 16];
    __shared__ float sDv[64];
    int tid = threadIdx.x;           // 256
    int row0 = blockIdx.x * 64;
    int col = tid & 63;
    float wreg[64];
#pragma unroll
    for (int k = 0; k < 64; k++) wreg[k] = __ldg(&Wm[k * 64 + col]);
    float bias = __ldg(&bv[col]);
    int nrows = min(64, N_NODES - row0);
    for (int idx = tid; idx < nrows * 16; idx += 256) {
        uint2 v = __ldg((const uint2*)(g_aggu + (size_t)row0 * 32) + idx);
        sIn[idx] = make_float4(bf_lo(v.x), bf_hi(v.x), bf_lo(v.y), bf_hi(v.y));
    }
    if (SCALE && tid < nrows) sDv[tid] = g_dinv[row0 + tid];
    __syncthreads();
    int rg = tid >> 6;
    for (int r = rg; r < nrows; r += 4) {
        float acc = bias;
#pragma unroll
        for (int k4 = 0; k4 < 16; k4++) {
            float4 v = sIn[r * 16 + k4];
            acc = fmaf(v.x, wreg[4 * k4 + 0], acc);
            acc = fmaf(v.y, wreg[4 * k4 + 1], acc);
            acc = fmaf(v.z, wreg[4 * k4 + 2], acc);
            acc = fmaf(v.w, wreg[4 * k4 + 3], acc);
        }
        acc = fmaxf(acc, 0.f);
        if (SCALE) acc *= sDv[r];
        // pair with neighbor column and store one bf16x2 per even thread
        float nxt = __shfl_down_sync(0xffffffffu, acc, 1);
        if ((tid & 1) == 0)
            out[(size_t)(row0 + r) * 32 + (col >> 1)] = bf2_pack(acc, nxt);
    }
}

// ---------------- fused mean pool + MLP head (last block does the head) ------
__global__ void k_pool_head(const int* __restrict__ batch,
                            const float* __restrict__ Wf1, const float* __restrict__ bf1,
                            const float* __restrict__ Wf2, const float* __restrict__ bf2,
                            float* __restrict__ out) {
    int g = blockIdx.x;
    int lo = 0, hi = N_NODES;
    while (lo < hi) { int mid = (lo + hi) >> 1; if (__ldg(&batch[mid]) < g) lo = mid + 1; else hi = mid; }
    int start = lo;
    lo = start; hi = N_NODES;
    while (lo < hi) { int mid = (lo + hi) >> 1; if (__ldg(&batch[mid]) < g + 1) lo = mid + 1; else hi = mid; }
    int end = lo;

    __shared__ float2 sp[8][32];
    int cp = threadIdx.x & 31, rg = threadIdx.x >> 5;
    float2 acc = make_float2(0.f, 0.f);
    for (int r = start + rg; r < end; r += 8) {
        unsigned u = __ldg(&g_ha[(size_t)r * 32 + cp]);
        acc.x += bf_lo(u); acc.y += bf_hi(u);
    }
    sp[rg][cp] = acc;
    __syncthreads();
    if (rg == 0) {
        float2 t = sp[0][cp];
#pragma unroll
        for (int i = 1; i < 8; i++) { t.x += sp[i][cp].x; t.y += sp[i][cp].y; }
        float cnt = (float)(end - start);
        if (cnt < 1.f) cnt = 1.f;
        ((float2*)g_pool)[g * 32 + cp] = make_float2(t.x / cnt, t.y / cnt);
    }

    // last block to finish runs the head
    __shared__ int s_last;
    __threadfence();
    __syncthreads();
    if (threadIdx.x == 0) s_last = (atomicAdd(&g_done, 1) == N_GRAPHS - 1);
    __syncthreads();
    if (!s_last) return;
    __threadfence();

    int gg = threadIdx.x;
    if (gg >= N_GRAPHS) return;
    float p[64];
#pragma unroll
    for (int k = 0; k < 64; k++) p[k] = g_pool[gg * 64 + k];
    float o = __ldg(&bf2[0]);
#pragma unroll 4
    for (int j = 0; j < 32; j++) {
        float hj = __ldg(&bf1[j]);
#pragma unroll
        for (int k = 0; k < 64; k++) hj = fmaf(p[k], __ldg(&Wf1[k * 32 + j]), hj);
        o = fmaf(fmaxf(hj, 0.f), __ldg(&Wf2[j]), o);
    }
    out[gg] = o;
}

// ---------------- launch ----------------
extern "C" void kernel_launch(void* const* d_in, const int* in_sizes, int n_in,
                              void* d_out, int out_size) {
    const float* x   = (const float*)d_in[0];
    const int*   ei  = (const int*)d_in[1];
    const int4*  src4 = (const int4*)ei;
    const int4*  dst4 = (const int4*)(ei + N_EDGES);
    const int*   batch = (const int*)d_in[3];
    const float* W1 = (const float*)d_in[4];  const float* b1 = (const float*)d_in[5];
    const float* W2 = (const float*)d_in[6];  const float* b2 = (const float*)d_in[7];
    const float* W3 = (const float*)d_in[8];  const float* b3 = (const float*)d_in[9];
    const float* Wf1 = (const float*)d_in[10]; const float* bf1 = (const float*)d_in[11];
    const float* Wf2 = (const float*)d_in[12]; const float* bf2 = (const float*)d_in[13];
    float* out = (float*)d_out;

    const int nb_scan = (N_NODES + 1023) / 1024;       // 98
    const int eb4 = (N_EDGES / 4) / 256;               // 3125
    const int wb = (N_NODES * 32 + 255) / 256;         // one warp per node: 12500
    const int mb = (N_NODES + 63) / 64;                // 1563

    k_zero_cnt<<<(N_NODES + 255) / 256, 256>>>();
    k_hist<<<eb4, 256>>>(dst4);
    k_scan_blocks<<<nb_scan, 1024>>>();
    k_scan_add<<<nb_scan, 1024>>>(x);
    k_fill<<<eb4, 256>>>(src4, dst4);

    k_agg16_mm1<<<wb, 256>>>(W1, b1);          // layer 1 fused -> ha (scaled)
    k_agg64<0><<<wb, 256>>>();                 // gather ha -> aggu
    k_mm64<1, 1><<<mb, 256>>>(W2, b2);         // aggu@W2 -> hb (scaled)
    k_agg64<1><<<wb, 256>>>();                 // gather hb -> aggu
    k_mm64<0, 0><<<mb, 256>>>(W3, b3);         // aggu@W3 -> ha (raw, for pool)

    k_pool_head<<<N_GRAPHS, 256>>>(batch, Wf1, bf1, Wf2, bf2, out);
}